// round 1
// baseline (speedup 1.0000x reference)
#include <cuda_runtime.h>
#include <math.h>

#define BATCH 2
#define SEQ 2048
#define DMODEL 768
#define NHEAD 12
#define DHEAD 64
#define MTOT (BATCH*SEQ)

// Scratch (device globals: allocation-free per harness rules)
__device__ float g_Q[MTOT*DMODEL];
__device__ float g_K[MTOT*DMODEL];
__device__ float g_V[MTOT*DMODEL];
__device__ float g_O[MTOT*DMODEL];

// ---------------------------------------------------------------------------
// Tiled SGEMM with bias: C[M,N] = A[M,K] @ W[K,N] + bias[N]
// BM=BN=64, BK=16, 256 threads, 4x4 micro-tile per thread.
// ---------------------------------------------------------------------------
#define BM 64
#define BN 64
#define BK 16

__global__ __launch_bounds__(256) void sgemm_bias(
    const float* __restrict__ A, const float* __restrict__ W,
    const float* __restrict__ bias, float* __restrict__ C,
    int M, int N, int K) {
  __shared__ float As[BM][BK+1];   // +1 pad: conflict-free strided access
  __shared__ float Bs[BK][BN];
  const int t  = threadIdx.x;
  const int tx = t & 15, ty = t >> 4;
  const int m0 = blockIdx.y * BM, n0 = blockIdx.x * BN;

  float acc[4][4] = {};

  const int am = t >> 2, ak = (t & 3) * 4;   // A tile: 64 rows x 4 float4 chunks
  const int bk = t >> 4, bn = (t & 15) * 4;  // B tile: 16 rows x 16 float4 chunks

  for (int k0 = 0; k0 < K; k0 += BK) {
    float4 a4 = *(const float4*)(A + (size_t)(m0+am)*K + k0 + ak);
    As[am][ak+0]=a4.x; As[am][ak+1]=a4.y; As[am][ak+2]=a4.z; As[am][ak+3]=a4.w;
    *(float4*)&Bs[bk][bn] = *(const float4*)(W + (size_t)(k0+bk)*N + n0 + bn);
    __syncthreads();

    #pragma unroll
    for (int k = 0; k < BK; k++) {
      float ra[4];
      #pragma unroll
      for (int i = 0; i < 4; i++) ra[i] = As[ty*4+i][k];   // broadcast reads
      float4 b4 = *(const float4*)&Bs[k][tx*4];             // LDS.128
      const float rb[4] = {b4.x, b4.y, b4.z, b4.w};
      #pragma unroll
      for (int i = 0; i < 4; i++)
        #pragma unroll
        for (int j = 0; j < 4; j++)
          acc[i][j] += ra[i] * rb[j];
    }
    __syncthreads();
  }

  #pragma unroll
  for (int i = 0; i < 4; i++) {
    const int m = m0 + ty*4 + i;
    #pragma unroll
    for (int j = 0; j < 4; j++) {
      const int n = n0 + tx*4 + j;
      C[(size_t)m*N + n] = acc[i][j] + bias[n];
    }
  }
}

// ---------------------------------------------------------------------------
// Flash attention (causal, NO 1/sqrt(dk) scaling -- faithful to reference).
// One thread per query row; BR=128 rows per CTA; key tiles of BC=32.
// q[64], o[64], s[32] live in registers; K/V tiles broadcast from SMEM.
// ---------------------------------------------------------------------------
#define BR 128
#define BC 32

__global__ __launch_bounds__(128) void flash_attn(
    const float* __restrict__ Q, const float* __restrict__ K,
    const float* __restrict__ V, float* __restrict__ O) {
  const int b    = blockIdx.z;
  const int h    = blockIdx.y;
  const int q0   = blockIdx.x * BR;
  const int tid  = threadIdx.x;
  const int qidx = q0 + tid;

  __shared__ float Ks[BC][DHEAD];
  __shared__ float Vs[BC][DHEAD];

  float q[DHEAD], o[DHEAD];
  const float* qp = Q + ((size_t)(b*SEQ + qidx))*DMODEL + h*DHEAD;
  #pragma unroll
  for (int d = 0; d < DHEAD; d += 4) {
    float4 v4 = *(const float4*)(qp + d);
    q[d]=v4.x; q[d+1]=v4.y; q[d+2]=v4.z; q[d+3]=v4.w;
    o[d]=0.f;  o[d+1]=0.f;  o[d+2]=0.f;  o[d+3]=0.f;
  }
  float m = -INFINITY, l = 0.f;

  const int ktiles = (q0 + BR) / BC;   // causal: only tiles with j0 < q0+BR
  for (int kt = 0; kt < ktiles; kt++) {
    const int j0 = kt * BC;

    // cooperative K/V tile load (coalesced float4)
    #pragma unroll
    for (int i = tid*4; i < BC*DHEAD; i += 128*4) {
      const int j = i >> 6, d = i & 63;
      const size_t base = ((size_t)(b*SEQ + j0 + j))*DMODEL + h*DHEAD + d;
      *(float4*)&Ks[j][d] = *(const float4*)(K + base);
      *(float4*)&Vs[j][d] = *(const float4*)(V + base);
    }
    __syncthreads();

    // scores: s[j] = q . K[j]   (LDS.128 broadcast, 4 FMA per LDS)
    float s[BC];
    #pragma unroll
    for (int j = 0; j < BC; j++) s[j] = 0.f;
    #pragma unroll 4
    for (int d = 0; d < DHEAD; d += 4) {
      const float qa=q[d], qb=q[d+1], qc=q[d+2], qd=q[d+3];
      #pragma unroll
      for (int j = 0; j < BC; j++) {
        float4 k4 = *(const float4*)&Ks[j][d];
        s[j] += qa*k4.x + qb*k4.y + qc*k4.z + qd*k4.w;
      }
    }

    // causal mask + online softmax update
    float mnew = m;
    #pragma unroll
    for (int j = 0; j < BC; j++) {
      s[j] = (j0 + j <= qidx) ? s[j] : -INFINITY;
      mnew = fmaxf(mnew, s[j]);
    }
    const float scale = __expf(m - mnew);   // m=-inf on first tile -> 0
    l *= scale;
    #pragma unroll
    for (int d = 0; d < DHEAD; d++) o[d] *= scale;

    #pragma unroll 4
    for (int j = 0; j < BC; j++) {
      const float p = __expf(s[j] - mnew);  // masked -> exp(-inf)=0
      l += p;
      #pragma unroll
      for (int d = 0; d < DHEAD; d += 4) {
        float4 v4 = *(const float4*)&Vs[j][d];
        o[d]+=p*v4.x; o[d+1]+=p*v4.y; o[d+2]+=p*v4.z; o[d+3]+=p*v4.w;
      }
    }
    m = mnew;
    __syncthreads();
  }

  const float inv = 1.0f / l;
  float* op = O + ((size_t)(b*SEQ + qidx))*DMODEL + h*DHEAD;
  #pragma unroll
  for (int d = 0; d < DHEAD; d += 4) {
    float4 v4 = make_float4(o[d]*inv, o[d+1]*inv, o[d+2]*inv, o[d+3]*inv);
    *(float4*)(op + d) = v4;
  }
}

// ---------------------------------------------------------------------------
// Launch: QKV projections -> flash attention -> output projection.
// Inputs (metadata order): query, key_, value, mask, W_q, b_q, W_k, b_k,
//                          W_v, b_v, W_o, b_o.  mask is causal -> handled
//                          analytically, input ignored.
// ---------------------------------------------------------------------------
extern "C" void kernel_launch(void* const* d_in, const int* in_sizes, int n_in,
                              void* d_out, int out_size) {
  const float* query = (const float*)d_in[0];
  const float* key_  = (const float*)d_in[1];
  const float* value = (const float*)d_in[2];
  // d_in[3] = mask (int32 causal tril) -- implemented analytically
  const float* W_q = (const float*)d_in[4];
  const float* b_q = (const float*)d_in[5];
  const float* W_k = (const float*)d_in[6];
  const float* b_k = (const float*)d_in[7];
  const float* W_v = (const float*)d_in[8];
  const float* b_v = (const float*)d_in[9];
  const float* W_o = (const float*)d_in[10];
  const float* b_o = (const float*)d_in[11];
  float* out = (float*)d_out;

  float *Qb, *Kb, *Vb, *Ob;
  cudaGetSymbolAddress((void**)&Qb, g_Q);
  cudaGetSymbolAddress((void**)&Kb, g_K);
  cudaGetSymbolAddress((void**)&Vb, g_V);
  cudaGetSymbolAddress((void**)&Ob, g_O);

  dim3 gemm_grid(DMODEL / BN, MTOT / BM);   // 12 x 64 blocks
  sgemm_bias<<<gemm_grid, 256>>>(query, W_q, b_q, Qb, MTOT, DMODEL, DMODEL);
  sgemm_bias<<<gemm_grid, 256>>>(key_,  W_k, b_k, Kb, MTOT, DMODEL, DMODEL);
  sgemm_bias<<<gemm_grid, 256>>>(value, W_v, b_v, Vb, MTOT, DMODEL, DMODEL);

  flash_attn<<<dim3(SEQ / BR, NHEAD, BATCH), BR>>>(Qb, Kb, Vb, Ob);

  sgemm_bias<<<gemm_grid, 256>>>(Ob, W_o, b_o, out, MTOT, DMODEL, DMODEL);
}

// round 2
// speedup vs baseline: 1.0177x; 1.0177x over previous
#include <cuda_runtime.h>
#include <math.h>

#define BATCH 2
#define SEQ 2048
#define DMODEL 768
#define NHEAD 12
#define DHEAD 64
#define MTOT (BATCH*SEQ)

typedef unsigned long long u64;

// ---- packed fp32x2 helpers (sm_103a FFMA2 path, PTX-only) ------------------
__device__ __forceinline__ void fma2(u64& d, u64 a, u64 b) {
  asm("fma.rn.f32x2 %0, %1, %2, %0;" : "+l"(d) : "l"(a), "l"(b));
}
__device__ __forceinline__ u64 mul2(u64 a, u64 b) {
  u64 r; asm("mul.rn.f32x2 %0, %1, %2;" : "=l"(r) : "l"(a), "l"(b)); return r;
}
__device__ __forceinline__ u64 bcast2(float x) {
  u64 r; asm("mov.b64 %0, {%1, %1};" : "=l"(r) : "f"(x)); return r;
}
__device__ __forceinline__ void unpack2(u64 v, float& lo, float& hi) {
  asm("mov.b64 {%0, %1}, %2;" : "=f"(lo), "=f"(hi) : "l"(v));
}

// Scratch (device globals: allocation-free per harness rules)
__device__ float g_Q[MTOT*DMODEL];
__device__ float g_K[MTOT*DMODEL];
__device__ float g_V[MTOT*DMODEL];
__device__ float g_O[MTOT*DMODEL];

// ---------------------------------------------------------------------------
// SGEMM v2: C[M,N] = A[M,K] @ W[K,N] + bias[N]
// 128x128 CTA tile, BK=8, 256 threads, 8x8 micro-tile (2x2 of 4x4),
// A transposed in SMEM, register prefetch, FFMA2 inner product.
// ---------------------------------------------------------------------------
#define GBM 128
#define GBN 128
#define GBK 8

__global__ __launch_bounds__(256) void sgemm_bias(
    const float* __restrict__ A, const float* __restrict__ W,
    const float* __restrict__ bias, float* __restrict__ C,
    int M, int N, int K) {
  __shared__ float As[GBK][GBM];   // transposed A tile
  __shared__ float Bs[GBK][GBN];

  const int t  = threadIdx.x;
  const int tx = t & 15, ty = t >> 4;
  const int m0 = blockIdx.y * GBM, n0 = blockIdx.x * GBN;

  // global-load assignments
  const int arow = t >> 1, acol = (t & 1) * 4;   // 128 rows x 2 float4 chunks
  const int brow = t >> 5, bcol = (t & 31) * 4;  // 8 rows x 32 float4 chunks
  const float* Ap = A + (size_t)(m0 + arow) * K + acol;
  const float* Wbase = W + n0 + bcol;

  u64 acc[8][4];
  #pragma unroll
  for (int i = 0; i < 8; i++)
    #pragma unroll
    for (int j = 0; j < 4; j++) acc[i][j] = 0ull;

  float4 a4 = *(const float4*)(Ap);
  float4 b4 = *(const float4*)(Wbase + (size_t)brow * N);

  for (int k0 = 0; k0 < K; k0 += GBK) {
    __syncthreads();
    As[acol+0][arow] = a4.x; As[acol+1][arow] = a4.y;
    As[acol+2][arow] = a4.z; As[acol+3][arow] = a4.w;
    *(float4*)&Bs[brow][bcol] = b4;
    __syncthreads();

    if (k0 + GBK < K) {  // prefetch next tile into registers
      a4 = *(const float4*)(Ap + k0 + GBK);
      b4 = *(const float4*)(Wbase + (size_t)(k0 + GBK + brow) * N);
    }

    #pragma unroll
    for (int k = 0; k < GBK; k++) {
      float4 a0 = *(const float4*)&As[k][ty*4];
      float4 a1 = *(const float4*)&As[k][ty*4 + 64];
      ulonglong2 bA = *(const ulonglong2*)&Bs[k][tx*4];
      ulonglong2 bB = *(const ulonglong2*)&Bs[k][tx*4 + 64];
      const float ra[8] = {a0.x,a0.y,a0.z,a0.w, a1.x,a1.y,a1.z,a1.w};
      #pragma unroll
      for (int i = 0; i < 8; i++) {
        u64 ai = bcast2(ra[i]);
        fma2(acc[i][0], ai, bA.x);
        fma2(acc[i][1], ai, bA.y);
        fma2(acc[i][2], ai, bB.x);
        fma2(acc[i][3], ai, bB.y);
      }
    }
  }

  // epilogue: unpack, add bias, STG.128
  #pragma unroll
  for (int i = 0; i < 8; i++) {
    const int m = m0 + ty*4 + (i & 3) + (i >> 2) * 64;
    #pragma unroll
    for (int g = 0; g < 2; g++) {
      const int n = n0 + g*64 + tx*4;
      float f0,f1,f2,f3;
      unpack2(acc[i][g*2+0], f0, f1);
      unpack2(acc[i][g*2+1], f2, f3);
      float4 bv = *(const float4*)(bias + n);
      float4 out = make_float4(f0+bv.x, f1+bv.y, f2+bv.z, f3+bv.w);
      *(float4*)(C + (size_t)m*N + n) = out;
    }
  }
}

// ---------------------------------------------------------------------------
// Flash attention (causal, unscaled -- faithful to reference).
// One thread per query row, BR=128 rows/CTA, BC=32 key tiles.
// q/o held as packed f32x2 pairs; FFMA2 for scores and PV accumulation.
// Reversed block order: heavy (late-q) CTAs start first.
// ---------------------------------------------------------------------------
#define BR 128
#define BC 32

__global__ __launch_bounds__(128) void flash_attn(
    const float* __restrict__ Q, const float* __restrict__ K,
    const float* __restrict__ V, float* __restrict__ O) {
  const int b    = blockIdx.z;
  const int h    = blockIdx.y;
  const int q0   = (gridDim.x - 1 - blockIdx.x) * BR;  // heavy blocks first
  const int tid  = threadIdx.x;
  const int qidx = q0 + tid;

  __shared__ float Ks[BC][DHEAD];
  __shared__ float Vs[BC][DHEAD];

  u64 q2[32], o2[32];
  const ulonglong2* qp =
      (const ulonglong2*)(Q + ((size_t)(b*SEQ + qidx))*DMODEL + h*DHEAD);
  #pragma unroll
  for (int c = 0; c < 16; c++) {
    ulonglong2 v = qp[c];
    q2[2*c] = v.x; q2[2*c+1] = v.y;
    o2[2*c] = 0ull; o2[2*c+1] = 0ull;
  }
  float m = -INFINITY, l = 0.f;

  const int ktiles = (q0 + BR) / BC;
  for (int kt = 0; kt < ktiles; kt++) {
    const int j0 = kt * BC;

    #pragma unroll
    for (int i = tid*4; i < BC*DHEAD; i += 128*4) {
      const int j = i >> 6, d = i & 63;
      const size_t base = ((size_t)(b*SEQ + j0 + j))*DMODEL + h*DHEAD + d;
      *(float4*)&Ks[j][d] = *(const float4*)(K + base);
      *(float4*)&Vs[j][d] = *(const float4*)(V + base);
    }
    __syncthreads();

    // scores: s[j] = q . K[j]  (FFMA2: 32 packed FMAs per row)
    float s[BC];
    #pragma unroll 4
    for (int j = 0; j < BC; j++) {
      u64 accp = 0ull;
      #pragma unroll
      for (int c = 0; c < 16; c++) {
        ulonglong2 kk = *(const ulonglong2*)&Ks[j][c*4];
        fma2(accp, q2[2*c],   kk.x);
        fma2(accp, q2[2*c+1], kk.y);
      }
      float lo, hi; unpack2(accp, lo, hi);
      s[j] = lo + hi;
    }

    // causal mask + online softmax update
    float mnew = m;
    #pragma unroll
    for (int j = 0; j < BC; j++) {
      s[j] = (j0 + j <= qidx) ? s[j] : -INFINITY;
      mnew = fmaxf(mnew, s[j]);
    }
    const float scale = __expf(m - mnew);
    l *= scale;
    const u64 sc2 = bcast2(scale);
    #pragma unroll
    for (int c = 0; c < 32; c++) o2[c] = mul2(o2[c], sc2);

    #pragma unroll 4
    for (int j = 0; j < BC; j++) {
      const float p = __expf(s[j] - mnew);
      l += p;
      const u64 p2 = bcast2(p);
      #pragma unroll
      for (int c = 0; c < 16; c++) {
        ulonglong2 vv = *(const ulonglong2*)&Vs[j][c*4];
        fma2(o2[2*c],   p2, vv.x);
        fma2(o2[2*c+1], p2, vv.y);
      }
    }
    m = mnew;
    __syncthreads();
  }

  const u64 inv2 = bcast2(1.0f / l);
  ulonglong2* op = (ulonglong2*)(O + ((size_t)(b*SEQ + qidx))*DMODEL + h*DHEAD);
  #pragma unroll
  for (int c = 0; c < 16; c++) {
    ulonglong2 v;
    v.x = mul2(o2[2*c],   inv2);
    v.y = mul2(o2[2*c+1], inv2);
    op[c] = v;
  }
}

// ---------------------------------------------------------------------------
// Launch: QKV projections -> flash attention -> output projection.
// ---------------------------------------------------------------------------
extern "C" void kernel_launch(void* const* d_in, const int* in_sizes, int n_in,
                              void* d_out, int out_size) {
  const float* query = (const float*)d_in[0];
  const float* key_  = (const float*)d_in[1];
  const float* value = (const float*)d_in[2];
  // d_in[3] = mask (causal tril) -- handled analytically
  const float* W_q = (const float*)d_in[4];
  const float* b_q = (const float*)d_in[5];
  const float* W_k = (const float*)d_in[6];
  const float* b_k = (const float*)d_in[7];
  const float* W_v = (const float*)d_in[8];
  const float* b_v = (const float*)d_in[9];
  const float* W_o = (const float*)d_in[10];
  const float* b_o = (const float*)d_in[11];
  float* out = (float*)d_out;

  float *Qb, *Kb, *Vb, *Ob;
  cudaGetSymbolAddress((void**)&Qb, g_Q);
  cudaGetSymbolAddress((void**)&Kb, g_K);
  cudaGetSymbolAddress((void**)&Vb, g_V);
  cudaGetSymbolAddress((void**)&Ob, g_O);

  dim3 gemm_grid(DMODEL / GBN, MTOT / GBM);   // 6 x 32 = 192 CTAs
  sgemm_bias<<<gemm_grid, 256>>>(query, W_q, b_q, Qb, MTOT, DMODEL, DMODEL);
  sgemm_bias<<<gemm_grid, 256>>>(key_,  W_k, b_k, Kb, MTOT, DMODEL, DMODEL);
  sgemm_bias<<<gemm_grid, 256>>>(value, W_v, b_v, Vb, MTOT, DMODEL, DMODEL);

  flash_attn<<<dim3(SEQ / BR, NHEAD, BATCH), BR>>>(Qb, Kb, Vb, Ob);

  sgemm_bias<<<gemm_grid, 256>>>(Ob, W_o, b_o, out, MTOT, DMODEL, DMODEL);
}